// round 13
// baseline (speedup 1.0000x reference)
#include <cuda_runtime.h>
#include <cstdint>

#define BB 4
#define NN 8192
#define FF 64
#define EE 65536
#define KK 4096
#define NW 256   // NN/32
#define KW 128   // KK/32
#define TGT (NN-KK)
#define FULLM 0xffffffffu
#define NBLK 128   // radix sort tiles per batch (512 keys each)

// ---------------- device scratch (static; no allocations) ----------------
__device__ unsigned long long g_keys[2][BB][EE];   // ping-pong
__device__ unsigned char g_ok[BB][EE];
__device__ unsigned g_sedge[BB][EE];               // packed (a | b<<13 | ok<<26), interior-first sorted
__device__ float g_vn[BB][NN];
__device__ int g_mask[BB][NN];
__device__ int g_m[BB][NN + 64];                   // +64 dummy slots for branchless greedy
__device__ int g_rank[BB][NN];
__device__ int g_gstart[BB][KK + 1];
__device__ unsigned short g_gsrc[BB][NN];
__device__ unsigned g_hist[BB][256 * NBLK];
__device__ unsigned g_histS[BB][256 * NBLK];
__device__ unsigned g_Ab[BB][NN][NW];              // 32 MB : row-major bits of A
__device__ unsigned g_G1[BB][KK][NW];              // 16 MB : row-merged
__device__ unsigned g_G1T[BB][NN][KW];             // 16 MB : transpose of G1
__device__ unsigned g_G2[BB][KK][KW];              // 8 MB  : col-merged (transposed final)
__device__ unsigned g_M2[BB][KK][KW];              // 8 MB  : final K x K bits (row-major)

// ---------------- utils ----------------
__device__ __forceinline__ unsigned warpScanIncl(unsigned v) {
    int lane = threadIdx.x & 31;
#pragma unroll
    for (int o = 1; o < 32; o <<= 1) {
        unsigned n = __shfl_up_sync(FULLM, v, o);
        if (lane >= o) v += n;
    }
    return v;
}

__device__ __forceinline__ unsigned blockScanExcl1024(unsigned v, unsigned* s_tmp, unsigned* total) {
    int tid = threadIdx.x, lane = tid & 31, wid = tid >> 5;
    __syncthreads();
    unsigned inc = warpScanIncl(v);
    if (lane == 31) s_tmp[wid] = inc;
    __syncthreads();
    if (wid == 0) {
        unsigned w = s_tmp[lane];
        unsigned wi = warpScanIncl(w);
        s_tmp[lane] = wi - w;
        if (lane == 31) s_tmp[32] = wi;
    }
    __syncthreads();
    *total = s_tmp[32];
    return inc - v + s_tmp[wid];
}

// ---------------- 1. vertex squared norms (XLA-order) + init m ----------------
__global__ void k_vnorm(const float* __restrict__ image) {
    int idx = blockIdx.x * blockDim.x + threadIdx.x;
    if (idx >= BB * NN) return;
    const float* row = image + (size_t)idx * FF;
    float p[32];
#pragma unroll
    for (int l = 0; l < 32; l++) {
        float a = row[l], c = row[l + 32];
        p[l] = __fadd_rn(__fmul_rn(a, a), __fmul_rn(c, c));
    }
#pragma unroll
    for (int off = 16; off >= 1; off >>= 1) {
#pragma unroll
        for (int l = 0; l < 16; l++) {
            if (l < off) p[l] = __fadd_rn(p[l], p[l + off]);
        }
    }
    g_vn[0][idx] = p[0];
    g_m[idx >> 13][idx & (NN - 1)] = idx & (NN - 1);
}

// ---------------- 2. keys (boundary edges pushed to tail) ----------------
__global__ void k_keys(const int* __restrict__ edges, const float* __restrict__ vs) {
    int idx = blockIdx.x * blockDim.x + threadIdx.x;
    int b = idx >> 16, e = idx & (EE - 1);
    if (b >= BB) return;
    int a = edges[(size_t)b * 2 * EE + e];
    int v1 = edges[(size_t)b * 2 * EE + EE + e];
    float c = __fadd_rn(g_vn[b][a], g_vn[b][v1]);
    float ax = vs[((size_t)b * NN + a) * 2 + 0], ay = vs[((size_t)b * NN + a) * 2 + 1];
    float bx = vs[((size_t)b * NN + v1) * 2 + 0], by = vs[((size_t)b * NN + v1) * 2 + 1];
    bool bndA = (ax < 0.05f) | (ax > 0.95f) | (ay < 0.05f) | (ay > 0.95f);
    bool bndB = (bx < 0.05f) | (bx > 0.95f) | (by < 0.05f) | (by > 0.95f);
    unsigned okv = (unsigned)(!(bndA | bndB));
    g_ok[b][e] = (unsigned char)okv;
    unsigned hi = okv ? __float_as_uint(c) : 0xFFFFFFFFu;
    g_keys[0][b][e] = ((unsigned long long)hi << 32) | (unsigned)e;
}

// ---------------- 3. multi-block stable LSD radix sort: 4 passes x 8-bit ----------------
__global__ void k_count(int p) {
    __shared__ unsigned s_h[256];
    int b = blockIdx.y, blk = blockIdx.x, t = threadIdx.x;
    s_h[t] = 0;
    __syncthreads();
    const unsigned long long* src = g_keys[p & 1][b];
    int sh = 32 + 8 * p;
    unsigned long long k0 = src[blk * 512 + t], k1 = src[blk * 512 + 256 + t];
    atomicAdd(&s_h[(unsigned)(k0 >> sh) & 255u], 1u);
    atomicAdd(&s_h[(unsigned)(k1 >> sh) & 255u], 1u);
    __syncthreads();
    g_hist[b][t * NBLK + blk] = s_h[t];
}

__global__ void __launch_bounds__(1024) k_scan() {
    __shared__ unsigned s_tmp[33];
    int b = blockIdx.x, t = threadIdx.x;
    unsigned v[32]; unsigned sum = 0;
    int base = t * 32;
#pragma unroll
    for (int i = 0; i < 32; i++) { v[i] = g_hist[b][base + i]; sum += v[i]; }
    unsigned tot;
    unsigned ex = blockScanExcl1024(sum, s_tmp, &tot);
    unsigned run = ex;
#pragma unroll
    for (int i = 0; i < 32; i++) { g_histS[b][base + i] = run; run += v[i]; }
}

// last pass writes g_sedge directly (fused gather)
__global__ void __launch_bounds__(256) k_scat(int p, const int* __restrict__ edges, int last) {
    __shared__ unsigned s_wcnt[8 * 256];
    __shared__ unsigned s_pre[8 * 256];
    __shared__ unsigned s_base[256];
    int b = blockIdx.y, blk = blockIdx.x, t = threadIdx.x, lane = t & 31, w = t >> 5;
    const unsigned long long* src = g_keys[p & 1][b];
    unsigned long long* dst = g_keys[(p + 1) & 1][b];
    int sh = 32 + 8 * p;
#pragma unroll
    for (int k = 0; k < 8; k++) s_wcnt[k * 256 + t] = 0;
    s_base[t] = g_histS[b][t * NBLK + blk];
    unsigned long long kk[2] = { src[blk * 512 + t], src[blk * 512 + 256 + t] };
    __syncthreads();
#pragma unroll
    for (int i = 0; i < 2; i++) {
        unsigned d = (unsigned)(kk[i] >> sh) & 255u;
        unsigned m = __match_any_sync(FULLM, d);
        unsigned below = (1u << lane) - 1u;
        unsigned rw = __popc(m & below);
        if (rw == 0) s_wcnt[w * 256 + d] = __popc(m);
        __syncthreads();
        unsigned run = s_base[t];
#pragma unroll
        for (int w2 = 0; w2 < 8; w2++) { s_pre[w2 * 256 + t] = run; run += s_wcnt[w2 * 256 + t]; }
        s_base[t] = run;
        __syncthreads();
        unsigned pos = s_pre[w * 256 + d] + rw;
        if (!last) {
            dst[pos] = kk[i];
        } else {
            unsigned eid = (unsigned)(kk[i] & 0xffffffffu);
            unsigned a = (unsigned)edges[(size_t)b * 2 * EE + eid];
            unsigned v1 = (unsigned)edges[(size_t)b * 2 * EE + EE + eid];
            g_sedge[b][pos] = a | (v1 << 13) | ((unsigned)g_ok[b][eid] << 26);
        }
        if (rw == 0) s_wcnt[w * 256 + d] = 0;
        __syncthreads();
    }
}

// ---------------- 4. greedy collapse: 64-edge windows, BRANCHLESS clean path ------------
__global__ void k_greedy() {
    __shared__ unsigned char s_mask[NN + 64];
    __shared__ unsigned char s_tagA[NN + 64];
    __shared__ unsigned char s_tagB[NN + 64];
    __shared__ unsigned char s_own[NN + 64];
    int bb = blockIdx.x, lane = threadIdx.x;
    for (int i = lane; i < NN + 64; i += 32) { s_mask[i] = 1; s_tagA[i] = 0xFF; s_tagB[i] = 0xFF; }
    __syncwarp();
    int nk = 0;
    const int W = EE / 64;
    int sid0 = lane, sid1 = 32 + lane;
    int d0 = NN + sid0, d1 = NN + sid1;
    unsigned cur0 = g_sedge[bb][lane],      cur1 = g_sedge[bb][32 + lane];
    unsigned nx0 = g_sedge[bb][64 + lane],  nx1 = g_sedge[bb][96 + lane];
    for (int w = 0; w < W; w++) {
        unsigned p0 = 0, p1 = 0;
        if (w + 2 < W) { p0 = g_sedge[bb][(w + 2) * 64 + lane]; p1 = g_sedge[bb][(w + 2) * 64 + 32 + lane]; }
        int a0 = cur0 & 8191, b0 = (cur0 >> 13) & 8191;
        int a1 = cur1 & 8191, b1 = (cur1 >> 13) & 8191;
        int ma0 = s_mask[a0], mb0 = s_mask[b0];
        int ma1 = s_mask[a1], mb1 = s_mask[b1];
        int t0 = ((cur0 >> 26) & 1) & ma0 & mb0;
        int t1 = ((cur1 >> 26) & 1) & ma1 & mb1;
        unsigned T0 = __ballot_sync(FULLM, t0);
        unsigned T1 = __ballot_sync(FULLM, t1);
        if (T0 | T1) {
            unsigned char w8 = (unsigned char)w;
            int ia0 = t0 ? a0 : d0, ib0 = t0 ? b0 : d0;
            int ia1 = t1 ? a1 : d1, ib1 = t1 ? b1 : d1;
            s_tagA[ia0] = w8; s_tagB[ib0] = w8; s_own[ib0] = (unsigned char)sid0;
            s_tagA[ia1] = w8; s_tagB[ib1] = w8; s_own[ib1] = (unsigned char)sid1;
            __syncwarp();
            int l0 = s_own[ib0] != (unsigned char)sid0;
            int l1 = s_own[ib1] != (unsigned char)sid1;
            s_tagA[l0 ? b0 : d0] = w8;
            s_tagA[l1 ? b1 : d1] = w8;
            __syncwarp();
            int f0 = t0 & (l0 | (s_tagA[b0] == w8) | (s_tagB[a0] == w8));
            int f1 = t1 & (l1 | (s_tagA[b1] == w8) | (s_tagB[a1] == w8));
            unsigned I0 = __ballot_sync(FULLM, f0);
            unsigned I1 = __ballot_sync(FULLM, f1);
            int cnt = __popc(T0) + __popc(T1);
            unsigned acc0 = 0, acc1 = 0;
            if (nk + cnt <= TGT) {
                if (!(I0 | I1)) {
                    acc0 = T0; acc1 = T1; nk += cnt;
                } else {
                    acc0 = T0 & ~I0; acc1 = T1 & ~I1;
                    nk += __popc(acc0) + __popc(acc1);
                    unsigned TT = I0;
                    while (TT) {
                        int t2 = __ffs(TT) - 1; TT &= TT - 1;
                        int at = __shfl_sync(FULLM, a0, t2);
                        int bt = __shfl_sync(FULLM, b0, t2);
                        unsigned conf = __ballot_sync(FULLM,
                            (((acc0 >> lane) & 1) && (b0 == at || b0 == bt)) ||
                            (((acc1 >> lane) & 1) && (b1 == at || b1 == bt)));
                        if (!conf) { acc0 |= 1u << t2; nk++; }
                    }
                    TT = I1;
                    while (TT) {
                        int t2 = __ffs(TT) - 1; TT &= TT - 1;
                        int at = __shfl_sync(FULLM, a1, t2);
                        int bt = __shfl_sync(FULLM, b1, t2);
                        unsigned conf = __ballot_sync(FULLM,
                            (((acc0 >> lane) & 1) && (b0 == at || b0 == bt)) ||
                            (((acc1 >> lane) & 1) && (b1 == at || b1 == bt)));
                        if (!conf) { acc1 |= 1u << t2; nk++; }
                    }
                }
            } else {
                unsigned TT = T0;
                while (TT) {
                    int t2 = __ffs(TT) - 1; TT &= TT - 1;
                    int at = __shfl_sync(FULLM, a0, t2);
                    int bt = __shfl_sync(FULLM, b0, t2);
                    unsigned conf = __ballot_sync(FULLM,
                        (((acc0 >> lane) & 1) && (b0 == at || b0 == bt)) ||
                        (((acc1 >> lane) & 1) && (b1 == at || b1 == bt)));
                    if (!conf && nk < TGT) { acc0 |= 1u << t2; nk++; }
                }
                TT = T1;
                while (TT) {
                    int t2 = __ffs(TT) - 1; TT &= TT - 1;
                    int at = __shfl_sync(FULLM, a1, t2);
                    int bt = __shfl_sync(FULLM, b1, t2);
                    unsigned conf = __ballot_sync(FULLM,
                        (((acc0 >> lane) & 1) && (b0 == at || b0 == bt)) ||
                        (((acc1 >> lane) & 1) && (b1 == at || b1 == bt)));
                    if (!conf && nk < TGT) { acc1 |= 1u << t2; nk++; }
                }
            }
            int A0 = (acc0 >> lane) & 1, A1 = (acc1 >> lane) & 1;
            s_mask[A0 ? b0 : d0] = 0;
            s_mask[A1 ? b1 : d1] = 0;
            g_m[bb][A0 ? b0 : d0] = a0;
            g_m[bb][A1 ? b1 : d1] = a1;
            __syncwarp();
            if (nk >= TGT) break;
        }
        cur0 = nx0; cur1 = nx1; nx0 = p0; nx1 = p1;
    }
    for (int i = lane; i < NN; i += 32) g_mask[bb][i] = s_mask[i];
}

// ---------------- 5. alive ranks + group CSR ----------------
__global__ void __launch_bounds__(1024) k_compact() {
    __shared__ unsigned s_tmp[33];
    __shared__ int s_cnt[KK];
    __shared__ int s_cur[KK];
    int b = blockIdx.x, tid = threadIdx.x;
    int base = tid * 8;
    unsigned mk[8]; unsigned c = 0;
#pragma unroll
    for (int i = 0; i < 8; i++) { mk[i] = (unsigned)g_mask[b][base + i]; c += mk[i]; }
    unsigned tot;
    unsigned ex = blockScanExcl1024(c, s_tmp, &tot);
    int run = (int)ex;
#pragma unroll
    for (int i = 0; i < 8; i++) { g_rank[b][base + i] = run; run += (int)mk[i]; }
    __syncthreads();
    for (int r = tid; r < KK; r += 1024) s_cnt[r] = 0;
    __syncthreads();
    for (int j = tid; j < NN; j += 1024) {
        int t = g_m[b][j];
        if (g_mask[b][t]) { int r = g_rank[b][t]; if (r < KK) atomicAdd(&s_cnt[r], 1); }
    }
    __syncthreads();
    int i4 = tid * 4; unsigned cv[4]; unsigned sum = 0;
#pragma unroll
    for (int i = 0; i < 4; i++) { cv[i] = (unsigned)s_cnt[i4 + i]; sum += cv[i]; }
    unsigned tot2;
    unsigned ex2 = blockScanExcl1024(sum, s_tmp, &tot2);
    int run2 = (int)ex2;
#pragma unroll
    for (int i = 0; i < 4; i++) { g_gstart[b][i4 + i] = run2; s_cur[i4 + i] = run2; run2 += (int)cv[i]; }
    if (tid == 1023) g_gstart[b][KK] = run2;
    __syncthreads();
    for (int j = tid; j < NN; j += 1024) {
        int t = g_m[b][j];
        if (g_mask[b][t]) {
            int r = g_rank[b][t];
            if (r < KK) { int pos = atomicAdd(&s_cur[r], 1); g_gsrc[b][pos] = (unsigned short)j; }
        }
    }
}

// ---------------- 6. pack A (f32 0/1) -> row-major bits via warp ballot ----------------
__global__ void __launch_bounds__(256) k_pack(const float* __restrict__ A) {
    int gw = (blockIdx.x * 256 + threadIdx.x) >> 5;
    int lane = threadIdx.x & 31;
    const float* base = A + (size_t)gw * 1024;
    unsigned myw = 0;
#pragma unroll
    for (int t = 0; t < 32; t++) {
        float v = base[t * 32 + lane];
        unsigned bal = __ballot_sync(FULLM, v != 0.0f);
        if (lane == t) myw = bal;
    }
    ((unsigned*)g_Ab)[(size_t)gw * 32 + lane] = myw;
}

// ---------------- 7. G1[r] = OR of A-bit rows in group(r)  (row merge) ----------------
__global__ void __launch_bounds__(1024) k_G1() {
    int b = blockIdx.y;
    int c = blockIdx.x * 4 + (threadIdx.x >> 8);
    int w = threadIdx.x & 255;
    int s = g_gstart[b][c], e = g_gstart[b][c + 1];
    unsigned v = 0;
    for (int i = s; i < e; i++) v |= g_Ab[b][g_gsrc[b][i]][w];
    g_G1[b][c][w] = v;
}

// ---------------- 8. bit transpose G1 (K x N) -> G1T (N x K) ----------------
__global__ void __launch_bounds__(1024) k_transT() {
    __shared__ __align__(16) unsigned wt[256 * 5];
    __shared__ __align__(16) unsigned outS[1024];
    int b = blockIdx.z, ct = blockIdx.y, jt = blockIdx.x;
    int tid = threadIdx.x;
    {
        int r = tid >> 2, w4 = tid & 3;
        wt[r * 5 + w4] = g_G1[b][ct * 256 + r][jt * 4 + w4];
    }
    __syncthreads();
    int w = tid >> 5, lane = tid & 31;
    int jw = w >> 3, iw = w & 7;
    unsigned s = wt[(iw * 32 + lane) * 5 + jw];
    unsigned myword = 0;
#pragma unroll 1
    for (int k = 0; k < 32; k++) {
        unsigned bt = __ballot_sync(FULLM, (s >> k) & 1);
        if (lane == k) myword = bt;
    }
    outS[(jw * 32 + lane) * 8 + iw] = myword;
    __syncthreads();
    int j = tid >> 3, ww = tid & 7;
    g_G1T[b][jt * 128 + j][ct * 8 + ww] = outS[tid];
}

// ---------------- 9. G2[c] = OR of G1T rows in group(c)  (col merge) ----------------
__global__ void __launch_bounds__(1024) k_G2() {
    int b = blockIdx.y;
    int r = blockIdx.x * 8 + (threadIdx.x >> 7);
    int w = threadIdx.x & 127;
    int s = g_gstart[b][r], e = g_gstart[b][r + 1];
    unsigned v = 0;
    for (int i = s; i < e; i++) v |= g_G1T[b][g_gsrc[b][i]][w];
    g_G2[b][r][w] = v;
}

// ---------------- 10. final K x K bit transpose: G2 -> M2 ----------------
__global__ void __launch_bounds__(1024) k_transKK() {
    __shared__ __align__(16) unsigned wt[256 * 5];
    __shared__ __align__(16) unsigned outS[1024];
    int b = blockIdx.z, ct = blockIdx.y, jt = blockIdx.x;
    int tid = threadIdx.x;
    {
        int r = tid >> 2, w4 = tid & 3;
        wt[r * 5 + w4] = g_G2[b][ct * 256 + r][jt * 4 + w4];
    }
    __syncthreads();
    int w = tid >> 5, lane = tid & 31;
    int jw = w >> 3, iw = w & 7;
    unsigned s = wt[(iw * 32 + lane) * 5 + jw];
    unsigned myword = 0;
#pragma unroll 1
    for (int k = 0; k < 32; k++) {
        unsigned bt = __ballot_sync(FULLM, (s >> k) & 1);
        if (lane == k) myword = bt;
    }
    outS[(jw * 32 + lane) * 8 + iw] = myword;
    __syncthreads();
    int j = tid >> 3, ww = tid & 7;
    g_M2[b][jt * 128 + j][ct * 8 + ww] = outS[tid];
}

// ---------------- 11a. pooled features (pack-independent; runs before join) ------------
__global__ void k_feat(const float* __restrict__ image, float* __restrict__ out) {
    int b = blockIdx.y;
    int idx = blockIdx.x * 256 + threadIdx.x;   // 0 .. K*F-1
    int f = idx & (FF - 1);
    int r = idx >> 6;
    int s = g_gstart[b][r], e = g_gstart[b][r + 1];
    float acc = 0.f;
    for (int i = s; i < e; i++) {
        int j = g_gsrc[b][i];
        acc += image[((size_t)b * NN + j) * FF + f];
    }
    out[(size_t)BB * KK * KK + ((size_t)b * KK + r) * FF + f] = acc;
}

// ---------------- 11b. expand bits -> float (diag cleared) ----------------
__global__ void k_expand(float* __restrict__ out) {
    int b = blockIdx.y;
    int idx = blockIdx.x * 256 + threadIdx.x;   // 0 .. K*K/4-1
    int r = idx >> 10;
    int c4 = (idx & 1023) << 2;
    unsigned wv = g_M2[b][r][c4 >> 5];
    int sh = c4 & 31;
    float4 o;
    o.x = (((wv >> (sh + 0)) & 1) && (r != c4 + 0)) ? 1.f : 0.f;
    o.y = (((wv >> (sh + 1)) & 1) && (r != c4 + 1)) ? 1.f : 0.f;
    o.z = (((wv >> (sh + 2)) & 1) && (r != c4 + 2)) ? 1.f : 0.f;
    o.w = (((wv >> (sh + 3)) & 1) && (r != c4 + 3)) ? 1.f : 0.f;
    ((float4*)out)[((size_t)b * KK + r) * (KK / 4) + (idx & 1023)] = o;
}

// ---------------- launch ----------------
extern "C" void kernel_launch(void* const* d_in, const int* in_sizes, int n_in,
                              void* d_out, int out_size) {
    const float* adj = (const float*)d_in[0];
    const float* image = (const float*)d_in[1];
    const float* vs = (const float*)d_in[2];
    const int* edges = (const int*)d_in[3];
    float* out = (float*)d_out;

    static cudaStream_t s1 = nullptr, s2 = nullptr;   // s1 = pack (LOW prio), s2 = chain (HIGH prio)
    static cudaEvent_t evF = nullptr, evJ = nullptr, evE = nullptr;
    if (!s1) {
        int pLeast = 0, pGreatest = 0;
        cudaDeviceGetStreamPriorityRange(&pLeast, &pGreatest);
        cudaStreamCreateWithPriority(&s1, cudaStreamNonBlocking, pLeast);     // lowest priority
        cudaStreamCreateWithPriority(&s2, cudaStreamNonBlocking, pGreatest);  // highest priority
        cudaEventCreateWithFlags(&evF, cudaEventDisableTiming);
        cudaEventCreateWithFlags(&evJ, cudaEventDisableTiming);
        cudaEventCreateWithFlags(&evE, cudaEventDisableTiming);
    }

    cudaEventRecord(evF, 0);
    cudaStreamWaitEvent(s2, evF, 0);

    k_vnorm<<<(BB * NN) / 256, 256, 0, s2>>>(image);              // #1
    k_keys<<<(BB * EE) / 256, 256, 0, s2>>>(edges, vs);           // #2
    k_count<<<dim3(NBLK, BB), 256, 0, s2>>>(0);                   // #3

    cudaStreamWaitEvent(s1, evF, 0);
    k_pack<<<32768, 256, 0, s1>>>(adj);                           // #4  <- ncu sample target

    k_scan<<<BB, 1024, 0, s2>>>();
    k_scat<<<dim3(NBLK, BB), 256, 0, s2>>>(0, edges, 0);
    for (int p = 1; p < 4; p++) {
        k_count<<<dim3(NBLK, BB), 256, 0, s2>>>(p);
        k_scan<<<BB, 1024, 0, s2>>>();
        k_scat<<<dim3(NBLK, BB), 256, 0, s2>>>(p, edges, p == 3);
    }
    k_greedy<<<BB, 32, 0, s2>>>();
    k_compact<<<BB, 1024, 0, s2>>>();
    k_feat<<<dim3((KK * FF) / 256, BB), 256, 0, s2>>>(image, out);  // pack-independent

    // join pack before merges
    cudaEventRecord(evJ, s1);
    cudaStreamWaitEvent(s2, evJ, 0);

    k_G1<<<dim3(KK / 4, BB), 1024, 0, s2>>>();
    k_transT<<<dim3(NN / 128, KK / 256, BB), 1024, 0, s2>>>();
    k_G2<<<dim3(KK / 8, BB), 1024, 0, s2>>>();
    k_transKK<<<dim3(KK / 128, KK / 256, BB), 1024, 0, s2>>>();
    k_expand<<<dim3((KK * KK / 4) / 256, BB), 256, 0, s2>>>(out);

    cudaEventRecord(evE, s2);
    cudaStreamWaitEvent(0, evE, 0);
}

// round 14
// speedup vs baseline: 1.3859x; 1.3859x over previous
#include <cuda_runtime.h>
#include <cstdint>

#define BB 4
#define NN 8192
#define FF 64
#define EE 65536
#define KK 4096
#define NW 256   // NN/32
#define KW 128   // KK/32
#define TGT (NN-KK)
#define FULLM 0xffffffffu
#define NBLK 128   // radix sort tiles per batch (512 keys each)

// ---------------- device scratch (static; no allocations) ----------------
__device__ unsigned long long g_keys[2][BB][EE];   // ping-pong
__device__ unsigned char g_ok[BB][EE];
__device__ unsigned g_sedge[BB][EE];               // packed (a | b<<13 | ok<<26), interior-first sorted
__device__ float g_vn[BB][NN];
__device__ int g_mask[BB][NN];
__device__ int g_m[BB][NN + 64];                   // +64 dummy slots for branchless greedy
__device__ int g_rank[BB][NN];
__device__ int g_gstart[BB][KK + 1];
__device__ unsigned short g_gsrc[BB][NN];
__device__ unsigned g_histM[4][BB][256 * NBLK];    // per-pass histograms, digit-major [d*NBLK+blk]
__device__ unsigned g_histS[BB][256 * NBLK];       // scanned, TRANSPOSED [blk*256+d]
__device__ unsigned g_Ab[BB][NN][NW];              // 32 MB : row-major bits of A
__device__ unsigned g_G1[BB][KK][NW];              // 16 MB : row-merged
__device__ unsigned g_G1T[BB][NN][KW];             // 16 MB : transpose of G1
__device__ unsigned g_G2[BB][KK][KW];              // 8 MB  : col-merged (transposed final)
__device__ unsigned g_M2[BB][KK][KW];              // 8 MB  : final K x K bits (row-major)

// ---------------- utils ----------------
__device__ __forceinline__ unsigned warpScanIncl(unsigned v) {
    int lane = threadIdx.x & 31;
#pragma unroll
    for (int o = 1; o < 32; o <<= 1) {
        unsigned n = __shfl_up_sync(FULLM, v, o);
        if (lane >= o) v += n;
    }
    return v;
}

__device__ __forceinline__ unsigned blockScanExcl1024(unsigned v, unsigned* s_tmp, unsigned* total) {
    int tid = threadIdx.x, lane = tid & 31, wid = tid >> 5;
    __syncthreads();
    unsigned inc = warpScanIncl(v);
    if (lane == 31) s_tmp[wid] = inc;
    __syncthreads();
    if (wid == 0) {
        unsigned w = s_tmp[lane];
        unsigned wi = warpScanIncl(w);
        s_tmp[lane] = wi - w;
        if (lane == 31) s_tmp[32] = wi;
    }
    __syncthreads();
    *total = s_tmp[32];
    return inc - v + s_tmp[wid];
}

// ---------------- 1. vertex squared norms (XLA-order) + init m + zero hists ------------
__global__ void k_vnorm(const float* __restrict__ image) {
    int idx = blockIdx.x * blockDim.x + threadIdx.x;
    if (idx >= BB * NN) return;
    // zero all 4 pass histograms (524288 entries / 32768 threads = 16 each)
    unsigned* hz = &g_histM[0][0][0];
#pragma unroll
    for (int z = 0; z < 16; z++) hz[idx * 16 + z] = 0;
    const float* row = image + (size_t)idx * FF;
    float p[32];
#pragma unroll
    for (int l = 0; l < 32; l++) {
        float a = row[l], c = row[l + 32];
        p[l] = __fadd_rn(__fmul_rn(a, a), __fmul_rn(c, c));
    }
#pragma unroll
    for (int off = 16; off >= 1; off >>= 1) {
#pragma unroll
        for (int l = 0; l < 16; l++) {
            if (l < off) p[l] = __fadd_rn(p[l], p[l + off]);
        }
    }
    g_vn[0][idx] = p[0];
    g_m[idx >> 13][idx & (NN - 1)] = idx & (NN - 1);
}

// ---------------- 2. keys (boundary to tail) + fused pass-0 histogram ----------------
__global__ void k_keys(const int* __restrict__ edges, const float* __restrict__ vs) {
    int idx = blockIdx.x * blockDim.x + threadIdx.x;
    int b = idx >> 16, e = idx & (EE - 1);
    if (b >= BB) return;
    int a = edges[(size_t)b * 2 * EE + e];
    int v1 = edges[(size_t)b * 2 * EE + EE + e];
    float c = __fadd_rn(g_vn[b][a], g_vn[b][v1]);
    float ax = vs[((size_t)b * NN + a) * 2 + 0], ay = vs[((size_t)b * NN + a) * 2 + 1];
    float bx = vs[((size_t)b * NN + v1) * 2 + 0], by = vs[((size_t)b * NN + v1) * 2 + 1];
    bool bndA = (ax < 0.05f) | (ax > 0.95f) | (ay < 0.05f) | (ay > 0.95f);
    bool bndB = (bx < 0.05f) | (bx > 0.95f) | (by < 0.05f) | (by > 0.95f);
    unsigned okv = (unsigned)(!(bndA | bndB));
    g_ok[b][e] = (unsigned char)okv;
    unsigned hi = okv ? __float_as_uint(c) : 0xFFFFFFFFu;
    g_keys[0][b][e] = ((unsigned long long)hi << 32) | (unsigned)e;
    atomicAdd(&g_histM[0][b][(hi & 255u) * NBLK + (e >> 9)], 1u);   // fused pass-0 count
}

// ---------------- 3a. scan pass-p histogram; write TRANSPOSED for coalesced scat -------
__global__ void __launch_bounds__(1024) k_scan(int p) {
    __shared__ unsigned s_tmp[33];
    int b = blockIdx.x, t = threadIdx.x;
    const unsigned* H = g_histM[p][b];
    unsigned v[32]; unsigned sum = 0;
    int base = t * 32;
#pragma unroll
    for (int i = 0; i < 32; i++) { v[i] = H[base + i]; sum += v[i]; }
    unsigned tot;
    unsigned ex = blockScanExcl1024(sum, s_tmp, &tot);
    unsigned run = ex;
#pragma unroll
    for (int i = 0; i < 32; i++) {
        int h = base + i;                          // h = d*128 + blk
        g_histS[b][(h & (NBLK - 1)) * 256 + (h >> 7)] = run;   // [blk*256+d]
        run += v[i];
    }
}

// ---------------- 3b. stable scatter, dual-element single prefix round ------------------
// Fused next-pass counting (p<3); last pass writes g_sedge directly.
__global__ void __launch_bounds__(256) k_scat(int p, const int* __restrict__ edges, int last) {
    __shared__ unsigned s_wcnt0[8 * 256];
    __shared__ unsigned s_wcnt1[8 * 256];
    __shared__ unsigned s_pre0[8 * 256];
    __shared__ unsigned s_pre1[8 * 256];
    __shared__ unsigned s_base[256];
    int b = blockIdx.y, blk = blockIdx.x, t = threadIdx.x, lane = t & 31, w = t >> 5;
    const unsigned long long* src = g_keys[p & 1][b];
    unsigned long long* dst = g_keys[(p + 1) & 1][b];
    int sh = 32 + 8 * p;
    // warp-local zero of own wcnt rows (no cross-warp hazard -> no block sync needed)
#pragma unroll
    for (int k = lane; k < 256; k += 32) { s_wcnt0[w * 256 + k] = 0; s_wcnt1[w * 256 + k] = 0; }
    s_base[t] = g_histS[b][blk * 256 + t];                 // coalesced
    unsigned long long k0 = src[blk * 512 + t], k1 = src[blk * 512 + 256 + t];
    unsigned d0 = (unsigned)(k0 >> sh) & 255u;
    unsigned d1 = (unsigned)(k1 >> sh) & 255u;
    unsigned m0 = __match_any_sync(FULLM, d0);
    unsigned m1 = __match_any_sync(FULLM, d1);
    unsigned below = (1u << lane) - 1u;
    unsigned rw0 = __popc(m0 & below);
    unsigned rw1 = __popc(m1 & below);
    if (rw0 == 0) s_wcnt0[w * 256 + d0] = __popc(m0);
    if (rw1 == 0) s_wcnt1[w * 256 + d1] = __popc(m1);
    __syncthreads();
    // stability order: el0 warp0..7, then el1 warp0..7 (matches source index order)
    unsigned run = s_base[t];
#pragma unroll
    for (int w2 = 0; w2 < 8; w2++) { s_pre0[w2 * 256 + t] = run; run += s_wcnt0[w2 * 256 + t]; }
#pragma unroll
    for (int w2 = 0; w2 < 8; w2++) { s_pre1[w2 * 256 + t] = run; run += s_wcnt1[w2 * 256 + t]; }
    __syncthreads();
    unsigned pos0 = s_pre0[w * 256 + d0] + rw0;
    unsigned pos1 = s_pre1[w * 256 + d1] + rw1;
    if (!last) {
        dst[pos0] = k0;
        dst[pos1] = k1;
        // fused next-pass histogram (destination tile = pos>>9)
        unsigned e0 = (unsigned)(k0 >> (sh + 8)) & 255u;
        unsigned e1 = (unsigned)(k1 >> (sh + 8)) & 255u;
        atomicAdd(&g_histM[p + 1][b][e0 * NBLK + (pos0 >> 9)], 1u);
        atomicAdd(&g_histM[p + 1][b][e1 * NBLK + (pos1 >> 9)], 1u);
    } else {
        unsigned eid0 = (unsigned)(k0 & 0xffffffffu);
        unsigned eid1 = (unsigned)(k1 & 0xffffffffu);
        unsigned a0 = (unsigned)edges[(size_t)b * 2 * EE + eid0];
        unsigned v0 = (unsigned)edges[(size_t)b * 2 * EE + EE + eid0];
        unsigned a1 = (unsigned)edges[(size_t)b * 2 * EE + eid1];
        unsigned v1 = (unsigned)edges[(size_t)b * 2 * EE + EE + eid1];
        g_sedge[b][pos0] = a0 | (v0 << 13) | ((unsigned)g_ok[b][eid0] << 26);
        g_sedge[b][pos1] = a1 | (v1 << 13) | ((unsigned)g_ok[b][eid1] << 26);
    }
}

// ---------------- 4. greedy collapse: 64-edge windows, BRANCHLESS clean path ------------
__global__ void k_greedy() {
    __shared__ unsigned char s_mask[NN + 64];
    __shared__ unsigned char s_tagA[NN + 64];
    __shared__ unsigned char s_tagB[NN + 64];
    __shared__ unsigned char s_own[NN + 64];
    int bb = blockIdx.x, lane = threadIdx.x;
    for (int i = lane; i < NN + 64; i += 32) { s_mask[i] = 1; s_tagA[i] = 0xFF; s_tagB[i] = 0xFF; }
    __syncwarp();
    int nk = 0;
    const int W = EE / 64;
    int sid0 = lane, sid1 = 32 + lane;
    int d0 = NN + sid0, d1 = NN + sid1;
    unsigned cur0 = g_sedge[bb][lane],      cur1 = g_sedge[bb][32 + lane];
    unsigned nx0 = g_sedge[bb][64 + lane],  nx1 = g_sedge[bb][96 + lane];
    for (int w = 0; w < W; w++) {
        unsigned p0 = 0, p1 = 0;
        if (w + 2 < W) { p0 = g_sedge[bb][(w + 2) * 64 + lane]; p1 = g_sedge[bb][(w + 2) * 64 + 32 + lane]; }
        int a0 = cur0 & 8191, b0 = (cur0 >> 13) & 8191;
        int a1 = cur1 & 8191, b1 = (cur1 >> 13) & 8191;
        int ma0 = s_mask[a0], mb0 = s_mask[b0];
        int ma1 = s_mask[a1], mb1 = s_mask[b1];
        int t0 = ((cur0 >> 26) & 1) & ma0 & mb0;
        int t1 = ((cur1 >> 26) & 1) & ma1 & mb1;
        unsigned T0 = __ballot_sync(FULLM, t0);
        unsigned T1 = __ballot_sync(FULLM, t1);
        if (T0 | T1) {
            unsigned char w8 = (unsigned char)w;
            int ia0 = t0 ? a0 : d0, ib0 = t0 ? b0 : d0;
            int ia1 = t1 ? a1 : d1, ib1 = t1 ? b1 : d1;
            s_tagA[ia0] = w8; s_tagB[ib0] = w8; s_own[ib0] = (unsigned char)sid0;
            s_tagA[ia1] = w8; s_tagB[ib1] = w8; s_own[ib1] = (unsigned char)sid1;
            __syncwarp();
            int l0 = s_own[ib0] != (unsigned char)sid0;
            int l1 = s_own[ib1] != (unsigned char)sid1;
            s_tagA[l0 ? b0 : d0] = w8;
            s_tagA[l1 ? b1 : d1] = w8;
            __syncwarp();
            int f0 = t0 & (l0 | (s_tagA[b0] == w8) | (s_tagB[a0] == w8));
            int f1 = t1 & (l1 | (s_tagA[b1] == w8) | (s_tagB[a1] == w8));
            unsigned I0 = __ballot_sync(FULLM, f0);
            unsigned I1 = __ballot_sync(FULLM, f1);
            int cnt = __popc(T0) + __popc(T1);
            unsigned acc0 = 0, acc1 = 0;
            if (nk + cnt <= TGT) {
                if (!(I0 | I1)) {
                    acc0 = T0; acc1 = T1; nk += cnt;
                } else {
                    acc0 = T0 & ~I0; acc1 = T1 & ~I1;
                    nk += __popc(acc0) + __popc(acc1);
                    unsigned TT = I0;
                    while (TT) {
                        int t2 = __ffs(TT) - 1; TT &= TT - 1;
                        int at = __shfl_sync(FULLM, a0, t2);
                        int bt = __shfl_sync(FULLM, b0, t2);
                        unsigned conf = __ballot_sync(FULLM,
                            (((acc0 >> lane) & 1) && (b0 == at || b0 == bt)) ||
                            (((acc1 >> lane) & 1) && (b1 == at || b1 == bt)));
                        if (!conf) { acc0 |= 1u << t2; nk++; }
                    }
                    TT = I1;
                    while (TT) {
                        int t2 = __ffs(TT) - 1; TT &= TT - 1;
                        int at = __shfl_sync(FULLM, a1, t2);
                        int bt = __shfl_sync(FULLM, b1, t2);
                        unsigned conf = __ballot_sync(FULLM,
                            (((acc0 >> lane) & 1) && (b0 == at || b0 == bt)) ||
                            (((acc1 >> lane) & 1) && (b1 == at || b1 == bt)));
                        if (!conf) { acc1 |= 1u << t2; nk++; }
                    }
                }
            } else {
                unsigned TT = T0;
                while (TT) {
                    int t2 = __ffs(TT) - 1; TT &= TT - 1;
                    int at = __shfl_sync(FULLM, a0, t2);
                    int bt = __shfl_sync(FULLM, b0, t2);
                    unsigned conf = __ballot_sync(FULLM,
                        (((acc0 >> lane) & 1) && (b0 == at || b0 == bt)) ||
                        (((acc1 >> lane) & 1) && (b1 == at || b1 == bt)));
                    if (!conf && nk < TGT) { acc0 |= 1u << t2; nk++; }
                }
                TT = T1;
                while (TT) {
                    int t2 = __ffs(TT) - 1; TT &= TT - 1;
                    int at = __shfl_sync(FULLM, a1, t2);
                    int bt = __shfl_sync(FULLM, b1, t2);
                    unsigned conf = __ballot_sync(FULLM,
                        (((acc0 >> lane) & 1) && (b0 == at || b0 == bt)) ||
                        (((acc1 >> lane) & 1) && (b1 == at || b1 == bt)));
                    if (!conf && nk < TGT) { acc1 |= 1u << t2; nk++; }
                }
            }
            int A0 = (acc0 >> lane) & 1, A1 = (acc1 >> lane) & 1;
            s_mask[A0 ? b0 : d0] = 0;
            s_mask[A1 ? b1 : d1] = 0;
            g_m[bb][A0 ? b0 : d0] = a0;
            g_m[bb][A1 ? b1 : d1] = a1;
            __syncwarp();
            if (nk >= TGT) break;
        }
        cur0 = nx0; cur1 = nx1; nx0 = p0; nx1 = p1;
    }
    for (int i = lane; i < NN; i += 32) g_mask[bb][i] = s_mask[i];
}

// ---------------- 5. alive ranks + group CSR ----------------
__global__ void __launch_bounds__(1024) k_compact() {
    __shared__ unsigned s_tmp[33];
    __shared__ int s_cnt[KK];
    __shared__ int s_cur[KK];
    int b = blockIdx.x, tid = threadIdx.x;
    int base = tid * 8;
    unsigned mk[8]; unsigned c = 0;
#pragma unroll
    for (int i = 0; i < 8; i++) { mk[i] = (unsigned)g_mask[b][base + i]; c += mk[i]; }
    unsigned tot;
    unsigned ex = blockScanExcl1024(c, s_tmp, &tot);
    int run = (int)ex;
#pragma unroll
    for (int i = 0; i < 8; i++) { g_rank[b][base + i] = run; run += (int)mk[i]; }
    __syncthreads();
    for (int r = tid; r < KK; r += 1024) s_cnt[r] = 0;
    __syncthreads();
    for (int j = tid; j < NN; j += 1024) {
        int t = g_m[b][j];
        if (g_mask[b][t]) { int r = g_rank[b][t]; if (r < KK) atomicAdd(&s_cnt[r], 1); }
    }
    __syncthreads();
    int i4 = tid * 4; unsigned cv[4]; unsigned sum = 0;
#pragma unroll
    for (int i = 0; i < 4; i++) { cv[i] = (unsigned)s_cnt[i4 + i]; sum += cv[i]; }
    unsigned tot2;
    unsigned ex2 = blockScanExcl1024(sum, s_tmp, &tot2);
    int run2 = (int)ex2;
#pragma unroll
    for (int i = 0; i < 4; i++) { g_gstart[b][i4 + i] = run2; s_cur[i4 + i] = run2; run2 += (int)cv[i]; }
    if (tid == 1023) g_gstart[b][KK] = run2;
    __syncthreads();
    for (int j = tid; j < NN; j += 1024) {
        int t = g_m[b][j];
        if (g_mask[b][t]) {
            int r = g_rank[b][t];
            if (r < KK) { int pos = atomicAdd(&s_cur[r], 1); g_gsrc[b][pos] = (unsigned short)j; }
        }
    }
}

// ---------------- 6. pack A (f32 0/1) -> row-major bits via warp ballot ----------------
__global__ void __launch_bounds__(256) k_pack(const float* __restrict__ A) {
    int gw = (blockIdx.x * 256 + threadIdx.x) >> 5;
    int lane = threadIdx.x & 31;
    const float* base = A + (size_t)gw * 1024;
    unsigned myw = 0;
#pragma unroll
    for (int t = 0; t < 32; t++) {
        float v = base[t * 32 + lane];
        unsigned bal = __ballot_sync(FULLM, v != 0.0f);
        if (lane == t) myw = bal;
    }
    ((unsigned*)g_Ab)[(size_t)gw * 32 + lane] = myw;
}

// ---------------- 7. G1[r] = OR of A-bit rows in group(r)  (row merge) ----------------
__global__ void __launch_bounds__(1024) k_G1() {
    int b = blockIdx.y;
    int c = blockIdx.x * 4 + (threadIdx.x >> 8);
    int w = threadIdx.x & 255;
    int s = g_gstart[b][c], e = g_gstart[b][c + 1];
    unsigned v = 0;
    for (int i = s; i < e; i++) v |= g_Ab[b][g_gsrc[b][i]][w];
    g_G1[b][c][w] = v;
}

// ---------------- 8. bit transpose G1 (K x N) -> G1T (N x K) ----------------
__global__ void __launch_bounds__(1024) k_transT() {
    __shared__ __align__(16) unsigned wt[256 * 5];
    __shared__ __align__(16) unsigned outS[1024];
    int b = blockIdx.z, ct = blockIdx.y, jt = blockIdx.x;
    int tid = threadIdx.x;
    {
        int r = tid >> 2, w4 = tid & 3;
        wt[r * 5 + w4] = g_G1[b][ct * 256 + r][jt * 4 + w4];
    }
    __syncthreads();
    int w = tid >> 5, lane = tid & 31;
    int jw = w >> 3, iw = w & 7;
    unsigned s = wt[(iw * 32 + lane) * 5 + jw];
    unsigned myword = 0;
#pragma unroll 1
    for (int k = 0; k < 32; k++) {
        unsigned bt = __ballot_sync(FULLM, (s >> k) & 1);
        if (lane == k) myword = bt;
    }
    outS[(jw * 32 + lane) * 8 + iw] = myword;
    __syncthreads();
    int j = tid >> 3, ww = tid & 7;
    g_G1T[b][jt * 128 + j][ct * 8 + ww] = outS[tid];
}

// ---------------- 9. G2[c] = OR of G1T rows in group(c)  (col merge) ----------------
__global__ void __launch_bounds__(1024) k_G2() {
    int b = blockIdx.y;
    int r = blockIdx.x * 8 + (threadIdx.x >> 7);
    int w = threadIdx.x & 127;
    int s = g_gstart[b][r], e = g_gstart[b][r + 1];
    unsigned v = 0;
    for (int i = s; i < e; i++) v |= g_G1T[b][g_gsrc[b][i]][w];
    g_G2[b][r][w] = v;
}

// ---------------- 10. final K x K bit transpose: G2 -> M2 ----------------
__global__ void __launch_bounds__(1024) k_transKK() {
    __shared__ __align__(16) unsigned wt[256 * 5];
    __shared__ __align__(16) unsigned outS[1024];
    int b = blockIdx.z, ct = blockIdx.y, jt = blockIdx.x;
    int tid = threadIdx.x;
    {
        int r = tid >> 2, w4 = tid & 3;
        wt[r * 5 + w4] = g_G2[b][ct * 256 + r][jt * 4 + w4];
    }
    __syncthreads();
    int w = tid >> 5, lane = tid & 31;
    int jw = w >> 3, iw = w & 7;
    unsigned s = wt[(iw * 32 + lane) * 5 + jw];
    unsigned myword = 0;
#pragma unroll 1
    for (int k = 0; k < 32; k++) {
        unsigned bt = __ballot_sync(FULLM, (s >> k) & 1);
        if (lane == k) myword = bt;
    }
    outS[(jw * 32 + lane) * 8 + iw] = myword;
    __syncthreads();
    int j = tid >> 3, ww = tid & 7;
    g_M2[b][jt * 128 + j][ct * 8 + ww] = outS[tid];
}

// ---------------- 11a. pooled features (pack-independent; before join) ----------------
__global__ void k_feat(const float* __restrict__ image, float* __restrict__ out) {
    int b = blockIdx.y;
    int idx = blockIdx.x * 256 + threadIdx.x;   // 0 .. K*F-1
    int f = idx & (FF - 1);
    int r = idx >> 6;
    int s = g_gstart[b][r], e = g_gstart[b][r + 1];
    float acc = 0.f;
    for (int i = s; i < e; i++) {
        int j = g_gsrc[b][i];
        acc += image[((size_t)b * NN + j) * FF + f];
    }
    out[(size_t)BB * KK * KK + ((size_t)b * KK + r) * FF + f] = acc;
}

// ---------------- 11b. expand bits -> float (diag cleared) ----------------
__global__ void k_expand(float* __restrict__ out) {
    int b = blockIdx.y;
    int idx = blockIdx.x * 256 + threadIdx.x;   // 0 .. K*K/4-1
    int r = idx >> 10;
    int c4 = (idx & 1023) << 2;
    unsigned wv = g_M2[b][r][c4 >> 5];
    int sh = c4 & 31;
    float4 o;
    o.x = (((wv >> (sh + 0)) & 1) && (r != c4 + 0)) ? 1.f : 0.f;
    o.y = (((wv >> (sh + 1)) & 1) && (r != c4 + 1)) ? 1.f : 0.f;
    o.z = (((wv >> (sh + 2)) & 1) && (r != c4 + 2)) ? 1.f : 0.f;
    o.w = (((wv >> (sh + 3)) & 1) && (r != c4 + 3)) ? 1.f : 0.f;
    ((float4*)out)[((size_t)b * KK + r) * (KK / 4) + (idx & 1023)] = o;
}

// ---------------- launch ----------------
extern "C" void kernel_launch(void* const* d_in, const int* in_sizes, int n_in,
                              void* d_out, int out_size) {
    const float* adj = (const float*)d_in[0];
    const float* image = (const float*)d_in[1];
    const float* vs = (const float*)d_in[2];
    const int* edges = (const int*)d_in[3];
    float* out = (float*)d_out;

    static cudaStream_t s1 = nullptr;
    static cudaEvent_t evF = nullptr, evJ = nullptr;
    if (!s1) {
        cudaStreamCreateWithFlags(&s1, cudaStreamNonBlocking);
        cudaEventCreateWithFlags(&evF, cudaEventDisableTiming);
        cudaEventCreateWithFlags(&evJ, cudaEventDisableTiming);
    }

    // fork point for pack = capture start (pack submitted later; execution overlaps)
    cudaEventRecord(evF, 0);

    k_vnorm<<<(BB * NN) / 256, 256>>>(image);                 // #1 (also zeros hists)
    k_keys<<<(BB * EE) / 256, 256>>>(edges, vs);              // #2 (fused pass-0 count)
    k_scan<<<BB, 1024>>>(0);                                  // #3
    k_scat<<<dim3(NBLK, BB), 256>>>(0, edges, 0);             // #4  <- ncu sample target
    for (int p = 1; p < 4; p++) {
        k_scan<<<BB, 1024>>>(p);
        k_scat<<<dim3(NBLK, BB), 256>>>(p, edges, p == 3);
    }
    k_greedy<<<BB, 32>>>();

    cudaStreamWaitEvent(s1, evF, 0);
    k_pack<<<32768, 256, 0, s1>>>(adj);                       // overlaps from capture start

    k_compact<<<BB, 1024>>>();
    k_feat<<<dim3((KK * FF) / 256, BB), 256>>>(image, out);   // pack-independent

    // join pack before merges
    cudaEventRecord(evJ, s1);
    cudaStreamWaitEvent(0, evJ, 0);

    k_G1<<<dim3(KK / 4, BB), 1024>>>();
    k_transT<<<dim3(NN / 128, KK / 256, BB), 1024>>>();
    k_G2<<<dim3(KK / 8, BB), 1024>>>();
    k_transKK<<<dim3(KK / 128, KK / 256, BB), 1024>>>();
    k_expand<<<dim3((KK * KK / 4) / 256, BB), 256>>>(out);
}